// round 2
// baseline (speedup 1.0000x reference)
#include <cuda_runtime.h>
#include <math.h>

#define NB 4
#define NH 16
#define SL 1024
#define DH 64
#define ED 1024
#define MTOT (NB*SL)          // 4096
#define BHN (NB*NH)           // 64

// ---- allocation-free scratch ----
__device__ float g_Q[(size_t)BHN*SL*DH];      // [B,H,L,Dh]
__device__ float g_K[(size_t)BHN*SL*DH];
__device__ float g_V[(size_t)BHN*SL*DH];
__device__ float g_posO[(size_t)MTOT*ED];     // [B,L,E] (head-merged)
__device__ float g_negO[(size_t)MTOT*ED];

// ============================================================
// C = A[M,K] @ W[N,K]^T + bias, 128x128 tile, 8x8 per thread.
// SCATTER: write C[m,n] into [B,H,L,Dh] layout (head split).
// ============================================================
template<bool SCATTER>
__global__ void gemm_xwT(const float* __restrict__ A,
                         const float* __restrict__ W,
                         const float* __restrict__ bias,
                         float* __restrict__ C, int K, int N)
{
    __shared__ float As[8][128];
    __shared__ float Ws[8][128];
    const int t   = threadIdx.x;          // 256 threads
    const int row0 = blockIdx.y * 128;
    const int col0 = blockIdx.x * 128;
    const int lr  = t >> 1;               // 0..127
    const int lc  = (t & 1) * 4;          // 0 or 4
    const int ty  = t >> 4;               // 0..15
    const int tx  = t & 15;               // 0..15

    float acc[8][8];
    #pragma unroll
    for (int i = 0; i < 8; i++)
        #pragma unroll
        for (int j = 0; j < 8; j++) acc[i][j] = 0.f;

    const float* Ap = A + (size_t)(row0 + lr) * K + lc;
    const float* Wp = W + (size_t)(col0 + lr) * K + lc;

    for (int k0 = 0; k0 < K; k0 += 8) {
        float4 a = *(const float4*)(Ap + k0);
        float4 w = *(const float4*)(Wp + k0);
        As[lc+0][lr] = a.x; As[lc+1][lr] = a.y; As[lc+2][lr] = a.z; As[lc+3][lr] = a.w;
        Ws[lc+0][lr] = w.x; Ws[lc+1][lr] = w.y; Ws[lc+2][lr] = w.z; Ws[lc+3][lr] = w.w;
        __syncthreads();
        #pragma unroll
        for (int kk = 0; kk < 8; kk++) {
            float4 a0 = *(const float4*)&As[kk][ty*4];
            float4 a1 = *(const float4*)&As[kk][64 + ty*4];
            float4 w0 = *(const float4*)&Ws[kk][tx*4];
            float4 w1 = *(const float4*)&Ws[kk][64 + tx*4];
            float ar[8] = {a0.x,a0.y,a0.z,a0.w, a1.x,a1.y,a1.z,a1.w};
            float wr[8] = {w0.x,w0.y,w0.z,w0.w, w1.x,w1.y,w1.z,w1.w};
            #pragma unroll
            for (int i = 0; i < 8; i++)
                #pragma unroll
                for (int j = 0; j < 8; j++)
                    acc[i][j] += ar[i] * wr[j];
        }
        __syncthreads();
    }

    #pragma unroll
    for (int i = 0; i < 8; i++) {
        int m = row0 + ((i < 4) ? (ty*4 + i) : (64 + ty*4 + i - 4));
        #pragma unroll
        for (int j = 0; j < 8; j++) {
            int n = col0 + ((j < 4) ? (tx*4 + j) : (64 + tx*4 + j - 4));
            float v = acc[i][j] + bias[n];
            if (SCATTER) {
                int b = m >> 10, l = m & 1023;
                int h = n >> 6,  d = n & 63;
                C[(((size_t)b*NH + h)*SL + l)*DH + d] = v;
            } else {
                C[(size_t)m*N + n] = v;
            }
        }
    }
}

// ============================================================
// S[b,h] = Q[b,h] @ K[b,h]^T * (1/8). 64x64 tile, K=64 fully in smem.
// Writes raw scaled scores into the pos_attn region of d_out.
// ============================================================
__global__ void scores_kernel(float* __restrict__ S)
{
    __shared__ float Qs[64][65];
    __shared__ float Ks[64][65];
    const int t  = threadIdx.x;          // 256
    const int bh = blockIdx.z;
    const int q0 = blockIdx.y * 64;
    const int k0 = blockIdx.x * 64;
    const float* Qh = g_Q + (size_t)bh * SL * DH;
    const float* Kh = g_K + (size_t)bh * SL * DH;

    #pragma unroll
    for (int i = 0; i < 4; i++) {
        int idx = t + i*256;             // float4 index, 1024 total
        int r = idx >> 4;
        int c = (idx & 15) * 4;
        float4 q = *(const float4*)(Qh + (size_t)(q0 + r)*DH + c);
        float4 k = *(const float4*)(Kh + (size_t)(k0 + r)*DH + c);
        Qs[r][c] = q.x; Qs[r][c+1] = q.y; Qs[r][c+2] = q.z; Qs[r][c+3] = q.w;
        Ks[r][c] = k.x; Ks[r][c+1] = k.y; Ks[r][c+2] = k.z; Ks[r][c+3] = k.w;
    }
    __syncthreads();

    const int ty = t >> 4, tx = t & 15;
    float acc[4][4];
    #pragma unroll
    for (int i = 0; i < 4; i++)
        #pragma unroll
        for (int j = 0; j < 4; j++) acc[i][j] = 0.f;

    #pragma unroll 8
    for (int kk = 0; kk < 64; kk++) {
        float q[4], kv[4];
        #pragma unroll
        for (int i = 0; i < 4; i++) q[i]  = Qs[ty*4 + i][kk];
        #pragma unroll
        for (int j = 0; j < 4; j++) kv[j] = Ks[tx*4 + j][kk];
        #pragma unroll
        for (int i = 0; i < 4; i++)
            #pragma unroll
            for (int j = 0; j < 4; j++)
                acc[i][j] += q[i] * kv[j];
    }

    const float scale = 0.125f;          // 1/sqrt(64)
    #pragma unroll
    for (int i = 0; i < 4; i++) {
        size_t rowbase = ((size_t)bh * SL + q0 + ty*4 + i) * SL + k0;
        #pragma unroll
        for (int j = 0; j < 4; j++)
            S[rowbase + tx*4 + j] = acc[i][j] * scale;
    }
}

// ============================================================
// Per-row: softmax -> pos_attn (in place); neg formula -> neg_attn.
// One block per (b,h,q) row of 1024; 256 threads x 4 elems.
// ============================================================
__global__ void softmax_neg_kernel(float* __restrict__ pos, float* __restrict__ neg)
{
    __shared__ float red[256];
    const int t = threadIdx.x;
    const size_t row = blockIdx.x;
    float* prow = pos + row * SL;
    float* nrow = neg + row * SL;

    float s[4];
    #pragma unroll
    for (int i = 0; i < 4; i++) s[i] = prow[t + i*256];

    // row max
    float m = fmaxf(fmaxf(s[0], s[1]), fmaxf(s[2], s[3]));
    red[t] = m; __syncthreads();
    for (int o = 128; o > 0; o >>= 1) { if (t < o) red[t] = fmaxf(red[t], red[t+o]); __syncthreads(); }
    m = red[0]; __syncthreads();

    // exp + sum
    float e[4]; float ls = 0.f;
    #pragma unroll
    for (int i = 0; i < 4; i++) { e[i] = expf(s[i] - m); ls += e[i]; }
    red[t] = ls; __syncthreads();
    for (int o = 128; o > 0; o >>= 1) { if (t < o) red[t] += red[t+o]; __syncthreads(); }
    float invS0 = 1.f / red[0]; __syncthreads();

    // p and sum(1-p)
    float p[4]; float l1 = 0.f;
    #pragma unroll
    for (int i = 0; i < 4; i++) { p[i] = e[i] * invS0; l1 += 1.f - p[i]; }
    red[t] = l1; __syncthreads();
    for (int o = 128; o > 0; o >>= 1) { if (t < o) red[t] += red[t+o]; __syncthreads(); }
    float invS1 = 1.f / red[0]; __syncthreads();

    // t = min((1-p)/S1, 1e-6/(p+1e-10)); sum
    float tv[4]; float l2 = 0.f;
    #pragma unroll
    for (int i = 0; i < 4; i++) {
        float a  = (1.f - p[i]) * invS1;
        float cb = 1e-6f / (p[i] + 1e-10f);
        tv[i] = fminf(a, cb);
        l2 += tv[i];
    }
    red[t] = l2; __syncthreads();
    for (int o = 128; o > 0; o >>= 1) { if (t < o) red[t] += red[t+o]; __syncthreads(); }
    float invS2 = 1.f / red[0];

    #pragma unroll
    for (int i = 0; i < 4; i++) {
        prow[t + i*256] = p[i];
        nrow[t + i*256] = tv[i] * invS2;
    }
}

// ============================================================
// O[b,h] = P[b,h](1024x1024) @ V[b,h](1024x64), written to [B,L,E] layout.
// blockIdx.z < 64: pos; else neg. 64(M) x 64(N) tile, K-tile 32.
// ============================================================
__global__ void av_kernel(const float* __restrict__ posA, const float* __restrict__ negA)
{
    __shared__ float Ps[64][33];
    __shared__ float Vs[32][65];
    const int t = threadIdx.x;
    const int z = blockIdx.z;
    const bool isPos = (z < BHN);
    const int bh = z & (BHN - 1);
    const float* P  = (isPos ? posA : negA) + (size_t)bh * SL * SL;
    const float* Vh = g_V + (size_t)bh * SL * DH;
    float* dst = isPos ? g_posO : g_negO;
    const int b = bh >> 4, h = bh & 15;
    const int m0 = blockIdx.y * 64;
    const int ty = t >> 4, tx = t & 15;

    float acc[4][4];
    #pragma unroll
    for (int i = 0; i < 4; i++)
        #pragma unroll
        for (int j = 0; j < 4; j++) acc[i][j] = 0.f;

    for (int k0 = 0; k0 < SL; k0 += 32) {
        #pragma unroll
        for (int i = 0; i < 2; i++) {           // P tile: 64x32 = 512 float4
            int idx = t + i*256;
            int r = idx >> 3;
            int c = (idx & 7) * 4;
            float4 pv = *(const float4*)(P + (size_t)(m0 + r)*SL + k0 + c);
            Ps[r][c] = pv.x; Ps[r][c+1] = pv.y; Ps[r][c+2] = pv.z; Ps[r][c+3] = pv.w;
        }
        #pragma unroll
        for (int i = 0; i < 2; i++) {           // V tile: 32x64 = 512 float4
            int idx = t + i*256;
            int r = idx >> 4;
            int c = (idx & 15) * 4;
            float4 vv = *(const float4*)(Vh + (size_t)(k0 + r)*DH + c);
            Vs[r][c] = vv.x; Vs[r][c+1] = vv.y; Vs[r][c+2] = vv.z; Vs[r][c+3] = vv.w;
        }
        __syncthreads();
        #pragma unroll 8
        for (int kk = 0; kk < 32; kk++) {
            float pr[4], vr[4];
            #pragma unroll
            for (int i = 0; i < 4; i++) pr[i] = Ps[ty*4 + i][kk];
            #pragma unroll
            for (int j = 0; j < 4; j++) vr[j] = Vs[kk][tx*4 + j];
            #pragma unroll
            for (int i = 0; i < 4; i++)
                #pragma unroll
                for (int j = 0; j < 4; j++)
                    acc[i][j] += pr[i] * vr[j];
        }
        __syncthreads();
    }

    #pragma unroll
    for (int i = 0; i < 4; i++) {
        size_t base = ((size_t)b*SL + m0 + ty*4 + i) * ED + (size_t)h*DH;
        #pragma unroll
        for (int j = 0; j < 4; j++)
            dst[base + tx*4 + j] = acc[i][j];
    }
}

// ============================================================
extern "C" void kernel_launch(void* const* d_in, const int* in_sizes, int n_in,
                              void* d_out, int out_size)
{
    const float* query = (const float*)d_in[0];
    const float* key   = (const float*)d_in[1];
    const float* value = (const float*)d_in[2];
    const float* Wq = (const float*)d_in[3];
    const float* bq = (const float*)d_in[4];
    const float* Wk = (const float*)d_in[5];
    const float* bk = (const float*)d_in[6];
    const float* Wv = (const float*)d_in[7];
    const float* bv = (const float*)d_in[8];
    const float* Wo = (const float*)d_in[9];
    const float* bo = (const float*)d_in[10];

    float* out = (float*)d_out;
    float* pos_output = out;
    float* neg_output = out + (size_t)MTOT * ED;
    float* pos_attn   = out + (size_t)2 * MTOT * ED;
    float* neg_attn   = pos_attn + (size_t)BHN * SL * SL;

    float *Qp, *Kp, *Vp, *pOp, *nOp;
    cudaGetSymbolAddress((void**)&Qp,  g_Q);
    cudaGetSymbolAddress((void**)&Kp,  g_K);
    cudaGetSymbolAddress((void**)&Vp,  g_V);
    cudaGetSymbolAddress((void**)&pOp, g_posO);
    cudaGetSymbolAddress((void**)&nOp, g_negO);

    dim3 gemmGrid(ED/128, MTOT/128);   // (8, 32)

    // Projections -> [B,H,L,Dh]
    gemm_xwT<true><<<gemmGrid, 256>>>(query, Wq, bq, Qp, ED, ED);
    gemm_xwT<true><<<gemmGrid, 256>>>(key,   Wk, bk, Kp, ED, ED);
    gemm_xwT<true><<<gemmGrid, 256>>>(value, Wv, bv, Vp, ED, ED);

    // Raw scaled scores into pos_attn region
    scores_kernel<<<dim3(SL/64, SL/64, BHN), 256>>>(pos_attn);

    // In-place softmax + neg-attn
    softmax_neg_kernel<<<BHN * SL, 256>>>(pos_attn, neg_attn);

    // attn @ V for pos and neg -> [B,L,E] scratch
    av_kernel<<<dim3(1, SL/64, 2*BHN), 256>>>(pos_attn, neg_attn);

    // Output projections
    gemm_xwT<false><<<gemmGrid, 256>>>(pOp, Wo, bo, pos_output, ED, ED);
    gemm_xwT<false><<<gemmGrid, 256>>>(nOp, Wo, bo, neg_output, ED, ED);
}